// round 1
// baseline (speedup 1.0000x reference)
#include <cuda_runtime.h>
#include <math.h>

// Problem constants
#define B_    2
#define T_    2048
#define H_    1024
#define NH_   16
#define HD_   64
#define WIN_  256

// Scratch (device globals — allocation-free per harness rules)
__device__ float g_qkv[(size_t)B_ * T_ * 3 * H_];   // [B,T,3H]
__device__ float g_att[(size_t)B_ * T_ * H_];       // [B,T,H] attention output

// ---------------------------------------------------------------------------
// SGEMM: C[M,N] = A[M,K] @ Bm[K,N] + bias[N]
// 128x128 block tile, K-tile 8, 256 threads, 8x8 register tile per thread.
// Requires M%128==0, N%128==0, K%8==0 (holds for all our shapes).
// ---------------------------------------------------------------------------
__global__ __launch_bounds__(256, 2)
void sgemm_bias_kernel(const float* __restrict__ A, const float* __restrict__ Bm,
                       const float* __restrict__ bias, float* __restrict__ C,
                       int M, int N, int K)
{
    __shared__ float As[8][128];   // transposed A tile: As[k][m]
    __shared__ float Bs[8][128];   // Bs[k][n]

    const int tid = threadIdx.x;
    const int bx  = blockIdx.x;    // N tile
    const int by  = blockIdx.y;    // M tile

    const int aRow = tid >> 1;           // 0..127
    const int aCol = (tid & 1) * 4;      // 0 or 4
    const int bRow = tid >> 5;           // 0..7
    const int bCol = (tid & 31) * 4;     // 0..124

    const int tx = tid & 15;             // 0..15 -> N direction
    const int ty = tid >> 4;             // 0..15 -> M direction

    const float* Ap = A + (size_t)(by * 128 + aRow) * K + aCol;
    const float* Bp = Bm + (size_t)bRow * N + bx * 128 + bCol;

    float acc[8][8];
#pragma unroll
    for (int i = 0; i < 8; i++)
#pragma unroll
        for (int j = 0; j < 8; j++) acc[i][j] = 0.f;

    for (int k0 = 0; k0 < K; k0 += 8) {
        float4 a4 = *(const float4*)(Ap + k0);
        float4 b4 = *(const float4*)(Bp + (size_t)k0 * N);

        As[aCol + 0][aRow] = a4.x;
        As[aCol + 1][aRow] = a4.y;
        As[aCol + 2][aRow] = a4.z;
        As[aCol + 3][aRow] = a4.w;
        *(float4*)&Bs[bRow][bCol] = b4;
        __syncthreads();

#pragma unroll
        for (int kk = 0; kk < 8; kk++) {
            float a[8], b[8];
#pragma unroll
            for (int i = 0; i < 8; i++) a[i] = As[kk][ty * 8 + i];
#pragma unroll
            for (int j = 0; j < 8; j++) b[j] = Bs[kk][tx * 8 + j];
#pragma unroll
            for (int i = 0; i < 8; i++)
#pragma unroll
                for (int j = 0; j < 8; j++)
                    acc[i][j] = fmaf(a[i], b[j], acc[i][j]);
        }
        __syncthreads();
    }

    // Epilogue with bias
#pragma unroll
    for (int i = 0; i < 8; i++) {
        const int row = by * 128 + ty * 8 + i;
        float* Cp = C + (size_t)row * N + bx * 128 + tx * 8;
        const float* bp = bias + bx * 128 + tx * 8;
#pragma unroll
        for (int j = 0; j < 8; j++) Cp[j] = acc[i][j] + bp[j];
    }
}

// ---------------------------------------------------------------------------
// Banded causal attention (flash-style online softmax).
// Grid: (T/64, NH, B). Block: 256 threads.
// Each block: 64 queries of one (batch, head). Key tiles kt in [qt-4, qt]
// (WINDOW=256 = 4 tiles of 64 + the diagonal tile).
// Dynamic smem: Qs[64][65] + KVs[64][65] + Ss[64][65] floats = 49920 B.
// ---------------------------------------------------------------------------
#define ATTN_SMEM (3 * 64 * 65 * 4)

__global__ __launch_bounds__(256)
void attn_kernel(float* __restrict__ out)
{
    extern __shared__ float sm[];
    float* Qs  = sm;                 // [64][65]
    float* KVs = sm + 64 * 65;       // [64][65] (K, then reused for V)
    float* Ss  = sm + 2 * 64 * 65;   // [64][65] scores -> probabilities

    __shared__ float m_sm[64], l_sm[64], sc_sm[64];

    const int qt  = blockIdx.x;
    const int h   = blockIdx.y;
    const int b   = blockIdx.z;
    const int tid = threadIdx.x;
    const int tx  = tid & 15;        // key-col / out-dim direction
    const int ty  = tid >> 4;        // query-row direction
    const int i0  = ty * 4;
    const int j0  = tx * 4;

    const size_t rowstride = 3 * H_;
    const size_t qbase = (size_t)(b * T_ + qt * 64) * rowstride + (size_t)h * HD_;

    // Load Q tile (coalesced over d)
    for (int idx = tid; idx < 64 * 64; idx += 256) {
        const int i = idx >> 6, d = idx & 63;
        Qs[i * 65 + d] = g_qkv[qbase + (size_t)i * rowstride + d];
    }
    if (tid < 64) { m_sm[tid] = -1e30f; l_sm[tid] = 0.f; }

    float acc[4][4];
#pragma unroll
    for (int r = 0; r < 4; r++)
#pragma unroll
        for (int c = 0; c < 4; c++) acc[r][c] = 0.f;

    __syncthreads();

    int kt0 = qt - 4; if (kt0 < 0) kt0 = 0;

    for (int kt = kt0; kt <= qt; kt++) {
        const size_t kbase = (size_t)(b * T_ + kt * 64) * rowstride + H_ + (size_t)h * HD_;
        // Load K tile
        for (int idx = tid; idx < 64 * 64; idx += 256) {
            const int j = idx >> 6, d = idx & 63;
            KVs[j * 65 + d] = g_qkv[kbase + (size_t)j * rowstride + d];
        }
        __syncthreads();

        // S = (Q K^T) * 1/sqrt(HD), masked to band [i-255, i]
        float s[4][4];
#pragma unroll
        for (int r = 0; r < 4; r++)
#pragma unroll
            for (int c = 0; c < 4; c++) s[r][c] = 0.f;

#pragma unroll 8
        for (int k = 0; k < 64; k++) {
            float a[4], bb[4];
#pragma unroll
            for (int r = 0; r < 4; r++) a[r]  = Qs[(i0 + r) * 65 + k];
#pragma unroll
            for (int c = 0; c < 4; c++) bb[c] = KVs[(j0 + c) * 65 + k];
#pragma unroll
            for (int r = 0; r < 4; r++)
#pragma unroll
                for (int c = 0; c < 4; c++)
                    s[r][c] = fmaf(a[r], bb[c], s[r][c]);
        }
#pragma unroll
        for (int r = 0; r < 4; r++) {
            const int ig = qt * 64 + i0 + r;
#pragma unroll
            for (int c = 0; c < 4; c++) {
                const int jg = kt * 64 + j0 + c;
                float v = s[r][c] * 0.125f;
                const int diff = ig - jg;
                if (diff < 0 || diff >= WIN_) v = -1e30f;
                Ss[(i0 + r) * 65 + j0 + c] = v;
            }
        }
        __syncthreads();

        // Per-row online softmax update (threads 0..63, one row each)
        if (tid < 64) {
            float* Sr = Ss + tid * 65;
            float mx = -1e30f;
#pragma unroll 8
            for (int j = 0; j < 64; j++) mx = fmaxf(mx, Sr[j]);
            const float mn = fmaxf(m_sm[tid], mx);
            const float sc = __expf(m_sm[tid] - mn);   // exp(0)=1 when both -1e30: safe
            float rs = 0.f;
#pragma unroll 8
            for (int j = 0; j < 64; j++) {
                const float p = __expf(Sr[j] - mn);
                Sr[j] = p;
                rs += p;
            }
            l_sm[tid]  = l_sm[tid] * sc + rs;
            m_sm[tid]  = mn;
            sc_sm[tid] = sc;
        }
        __syncthreads();

        // Load V over K tile buffer; rescale accumulators meanwhile
        const size_t vbase = (size_t)(b * T_ + kt * 64) * rowstride + 2 * H_ + (size_t)h * HD_;
        for (int idx = tid; idx < 64 * 64; idx += 256) {
            const int j = idx >> 6, d = idx & 63;
            KVs[j * 65 + d] = g_qkv[vbase + (size_t)j * rowstride + d];
        }
#pragma unroll
        for (int r = 0; r < 4; r++) {
            const float sc = sc_sm[i0 + r];
#pragma unroll
            for (int c = 0; c < 4; c++) acc[r][c] *= sc;
        }
        __syncthreads();

        // O += P @ V
#pragma unroll 8
        for (int k = 0; k < 64; k++) {
            float p[4], vv[4];
#pragma unroll
            for (int r = 0; r < 4; r++) p[r]  = Ss[(i0 + r) * 65 + k];
#pragma unroll
            for (int c = 0; c < 4; c++) vv[c] = KVs[k * 65 + j0 + c];
#pragma unroll
            for (int r = 0; r < 4; r++)
#pragma unroll
                for (int c = 0; c < 4; c++)
                    acc[r][c] = fmaf(p[r], vv[c], acc[r][c]);
        }
        __syncthreads();   // KVs/Ss reused next iteration
    }

    // Normalize and write out[b][qt*64+i][h*64 + d]
#pragma unroll
    for (int r = 0; r < 4; r++) {
        const float inv = 1.f / l_sm[i0 + r];
        const int trow = qt * 64 + i0 + r;
        float* op = out + (size_t)(b * T_ + trow) * H_ + (size_t)h * HD_ + j0;
#pragma unroll
        for (int c = 0; c < 4; c++) op[c] = acc[r][c] * inv;
    }
}

// ---------------------------------------------------------------------------
// Launch: qkv GEMM -> banded attention -> out GEMM
// ---------------------------------------------------------------------------
extern "C" void kernel_launch(void* const* d_in, const int* in_sizes, int n_in,
                              void* d_out, int out_size)
{
    const float* x     = (const float*)d_in[0];   // [B,T,H]
    const float* W_qkv = (const float*)d_in[1];   // [H,3H]
    const float* b_qkv = (const float*)d_in[2];   // [3H]
    const float* W_out = (const float*)d_in[3];   // [H,H]
    const float* b_out = (const float*)d_in[4];   // [H]
    float* out = (float*)d_out;                   // [B,T,H]

    float* qkv; cudaGetSymbolAddress((void**)&qkv, g_qkv);
    float* att; cudaGetSymbolAddress((void**)&att, g_att);

    const int M = B_ * T_;   // 4096

    // 1) QKV projection: [4096,1024] @ [1024,3072] + bias
    {
        dim3 grid((3 * H_) / 128, M / 128);  // (24, 32)
        sgemm_bias_kernel<<<grid, 256>>>(x, W_qkv, b_qkv, qkv, M, 3 * H_, H_);
    }

    // 2) Banded causal attention
    {
        cudaFuncSetAttribute(attn_kernel,
                             cudaFuncAttributeMaxDynamicSharedMemorySize, ATTN_SMEM);
        dim3 grid(T_ / 64, NH_, B_);         // (32, 16, 2)
        attn_kernel<<<grid, 256, ATTN_SMEM>>>(att);
    }

    // 3) Output projection: [4096,1024] @ [1024,1024] + bias
    {
        dim3 grid(H_ / 128, M / 128);        // (8, 32)
        sgemm_bias_kernel<<<grid, 256>>>(att, W_out, b_out, out, M, H_, H_);
    }
}

// round 2
// speedup vs baseline: 1.0027x; 1.0027x over previous
#include <cuda_runtime.h>
#include <math.h>

// Problem constants
#define B_    2
#define T_    2048
#define H_    1024
#define NH_   16
#define HD_   64
#define WIN_  256

// Scratch (device globals — allocation-free per harness rules)
__device__ float g_qkv[(size_t)B_ * T_ * 3 * H_];   // [B,T,3H]
__device__ float g_att[(size_t)B_ * T_ * H_];       // [B,T,H] attention output

// ---------------------------------------------------------------------------
// SGEMM: C[M,N] = A[M,K] @ Bm[K,N] + bias[N]
// 128x128 block tile, K-tile 8, 256 threads, 8x8 register tile per thread.
// Requires M%128==0, N%128==0, K%8==0 (holds for all our shapes).
// ---------------------------------------------------------------------------
__global__ __launch_bounds__(256, 2)
void sgemm_bias_kernel(const float* __restrict__ A, const float* __restrict__ Bm,
                       const float* __restrict__ bias, float* __restrict__ C,
                       int M, int N, int K)
{
    __shared__ float As[8][128];   // transposed A tile: As[k][m]
    __shared__ float Bs[8][128];   // Bs[k][n]

    const int tid = threadIdx.x;
    const int bx  = blockIdx.x;    // N tile
    const int by  = blockIdx.y;    // M tile

    const int aRow = tid >> 1;           // 0..127
    const int aCol = (tid & 1) * 4;      // 0 or 4
    const int bRow = tid >> 5;           // 0..7
    const int bCol = (tid & 31) * 4;     // 0..124

    const int tx = tid & 15;             // 0..15 -> N direction
    const int ty = tid >> 4;             // 0..15 -> M direction

    const float* Ap = A + (size_t)(by * 128 + aRow) * K + aCol;
    const float* Bp = Bm + (size_t)bRow * N + bx * 128 + bCol;

    float acc[8][8];
#pragma unroll
    for (int i = 0; i < 8; i++)
#pragma unroll
        for (int j = 0; j < 8; j++) acc[i][j] = 0.f;

    for (int k0 = 0; k0 < K; k0 += 8) {
        float4 a4 = *(const float4*)(Ap + k0);
        float4 b4 = *(const float4*)(Bp + (size_t)k0 * N);

        As[aCol + 0][aRow] = a4.x;
        As[aCol + 1][aRow] = a4.y;
        As[aCol + 2][aRow] = a4.z;
        As[aCol + 3][aRow] = a4.w;
        *(float4*)&Bs[bRow][bCol] = b4;
        __syncthreads();

#pragma unroll
        for (int kk = 0; kk < 8; kk++) {
            float a[8], b[8];
#pragma unroll
            for (int i = 0; i < 8; i++) a[i] = As[kk][ty * 8 + i];
#pragma unroll
            for (int j = 0; j < 8; j++) b[j] = Bs[kk][tx * 8 + j];
#pragma unroll
            for (int i = 0; i < 8; i++)
#pragma unroll
                for (int j = 0; j < 8; j++)
                    acc[i][j] = fmaf(a[i], b[j], acc[i][j]);
        }
        __syncthreads();
    }

    // Epilogue with bias
#pragma unroll
    for (int i = 0; i < 8; i++) {
        const int row = by * 128 + ty * 8 + i;
        float* Cp = C + (size_t)row * N + bx * 128 + tx * 8;
        const float* bp = bias + bx * 128 + tx * 8;
#pragma unroll
        for (int j = 0; j < 8; j++) Cp[j] = acc[i][j] + bp[j];
    }
}

// ---------------------------------------------------------------------------
// Banded causal attention (flash-style online softmax).
// Grid: (T/64, NH, B). Block: 256 threads.
// Each block: 64 queries of one (batch, head). Key tiles kt in [qt-4, qt]
// (WINDOW=256 = 4 tiles of 64 + the diagonal tile).
// Dynamic smem: Qs[64][65] + KVs[64][65] + Ss[64][65] floats = 49920 B.
// ---------------------------------------------------------------------------
#define ATTN_SMEM (3 * 64 * 65 * 4)

__global__ __launch_bounds__(256)
void attn_kernel(float* __restrict__ out)
{
    extern __shared__ float sm[];
    float* Qs  = sm;                 // [64][65]
    float* KVs = sm + 64 * 65;       // [64][65] (K, then reused for V)
    float* Ss  = sm + 2 * 64 * 65;   // [64][65] scores -> probabilities

    __shared__ float m_sm[64], l_sm[64], sc_sm[64];

    const int qt  = blockIdx.x;
    const int h   = blockIdx.y;
    const int b   = blockIdx.z;
    const int tid = threadIdx.x;
    const int tx  = tid & 15;        // key-col / out-dim direction
    const int ty  = tid >> 4;        // query-row direction
    const int i0  = ty * 4;
    const int j0  = tx * 4;

    const size_t rowstride = 3 * H_;
    const size_t qbase = (size_t)(b * T_ + qt * 64) * rowstride + (size_t)h * HD_;

    // Load Q tile (coalesced over d)
    for (int idx = tid; idx < 64 * 64; idx += 256) {
        const int i = idx >> 6, d = idx & 63;
        Qs[i * 65 + d] = g_qkv[qbase + (size_t)i * rowstride + d];
    }
    if (tid < 64) { m_sm[tid] = -1e30f; l_sm[tid] = 0.f; }

    float acc[4][4];
#pragma unroll
    for (int r = 0; r < 4; r++)
#pragma unroll
        for (int c = 0; c < 4; c++) acc[r][c] = 0.f;

    __syncthreads();

    int kt0 = qt - 4; if (kt0 < 0) kt0 = 0;

    for (int kt = kt0; kt <= qt; kt++) {
        const size_t kbase = (size_t)(b * T_ + kt * 64) * rowstride + H_ + (size_t)h * HD_;
        // Load K tile
        for (int idx = tid; idx < 64 * 64; idx += 256) {
            const int j = idx >> 6, d = idx & 63;
            KVs[j * 65 + d] = g_qkv[kbase + (size_t)j * rowstride + d];
        }
        __syncthreads();

        // S = (Q K^T) * 1/sqrt(HD), masked to band [i-255, i]
        float s[4][4];
#pragma unroll
        for (int r = 0; r < 4; r++)
#pragma unroll
            for (int c = 0; c < 4; c++) s[r][c] = 0.f;

#pragma unroll 8
        for (int k = 0; k < 64; k++) {
            float a[4], bb[4];
#pragma unroll
            for (int r = 0; r < 4; r++) a[r]  = Qs[(i0 + r) * 65 + k];
#pragma unroll
            for (int c = 0; c < 4; c++) bb[c] = KVs[(j0 + c) * 65 + k];
#pragma unroll
            for (int r = 0; r < 4; r++)
#pragma unroll
                for (int c = 0; c < 4; c++)
                    s[r][c] = fmaf(a[r], bb[c], s[r][c]);
        }
#pragma unroll
        for (int r = 0; r < 4; r++) {
            const int ig = qt * 64 + i0 + r;
#pragma unroll
            for (int c = 0; c < 4; c++) {
                const int jg = kt * 64 + j0 + c;
                float v = s[r][c] * 0.125f;
                const int diff = ig - jg;
                if (diff < 0 || diff >= WIN_) v = -1e30f;
                Ss[(i0 + r) * 65 + j0 + c] = v;
            }
        }
        __syncthreads();

        // Per-row online softmax update (threads 0..63, one row each)
        if (tid < 64) {
            float* Sr = Ss + tid * 65;
            float mx = -1e30f;
#pragma unroll 8
            for (int j = 0; j < 64; j++) mx = fmaxf(mx, Sr[j]);
            const float mn = fmaxf(m_sm[tid], mx);
            const float sc = __expf(m_sm[tid] - mn);   // exp(0)=1 when both -1e30: safe
            float rs = 0.f;
#pragma unroll 8
            for (int j = 0; j < 64; j++) {
                const float p = __expf(Sr[j] - mn);
                Sr[j] = p;
                rs += p;
            }
            l_sm[tid]  = l_sm[tid] * sc + rs;
            m_sm[tid]  = mn;
            sc_sm[tid] = sc;
        }
        __syncthreads();

        // Load V over K tile buffer; rescale accumulators meanwhile
        const size_t vbase = (size_t)(b * T_ + kt * 64) * rowstride + 2 * H_ + (size_t)h * HD_;
        for (int idx = tid; idx < 64 * 64; idx += 256) {
            const int j = idx >> 6, d = idx & 63;
            KVs[j * 65 + d] = g_qkv[vbase + (size_t)j * rowstride + d];
        }
#pragma unroll
        for (int r = 0; r < 4; r++) {
            const float sc = sc_sm[i0 + r];
#pragma unroll
            for (int c = 0; c < 4; c++) acc[r][c] *= sc;
        }
        __syncthreads();

        // O += P @ V
#pragma unroll 8
        for (int k = 0; k < 64; k++) {
            float p[4], vv[4];
#pragma unroll
            for (int r = 0; r < 4; r++) p[r]  = Ss[(i0 + r) * 65 + k];
#pragma unroll
            for (int c = 0; c < 4; c++) vv[c] = KVs[k * 65 + j0 + c];
#pragma unroll
            for (int r = 0; r < 4; r++)
#pragma unroll
                for (int c = 0; c < 4; c++)
                    acc[r][c] = fmaf(p[r], vv[c], acc[r][c]);
        }
        __syncthreads();   // KVs/Ss reused next iteration
    }

    // Normalize and write out[b][qt*64+i][h*64 + d]
#pragma unroll
    for (int r = 0; r < 4; r++) {
        const float inv = 1.f / l_sm[i0 + r];
        const int trow = qt * 64 + i0 + r;
        float* op = out + (size_t)(b * T_ + trow) * H_ + (size_t)h * HD_ + j0;
#pragma unroll
        for (int c = 0; c < 4; c++) op[c] = acc[r][c] * inv;
    }
}

// ---------------------------------------------------------------------------
// Launch: qkv GEMM -> banded attention -> out GEMM
// ---------------------------------------------------------------------------
extern "C" void kernel_launch(void* const* d_in, const int* in_sizes, int n_in,
                              void* d_out, int out_size)
{
    const float* x     = (const float*)d_in[0];   // [B,T,H]
    const float* W_qkv = (const float*)d_in[1];   // [H,3H]
    const float* b_qkv = (const float*)d_in[2];   // [3H]
    const float* W_out = (const float*)d_in[3];   // [H,H]
    const float* b_out = (const float*)d_in[4];   // [H]
    float* out = (float*)d_out;                   // [B,T,H]

    float* qkv; cudaGetSymbolAddress((void**)&qkv, g_qkv);
    float* att; cudaGetSymbolAddress((void**)&att, g_att);

    const int M = B_ * T_;   // 4096

    // 1) QKV projection: [4096,1024] @ [1024,3072] + bias
    {
        dim3 grid((3 * H_) / 128, M / 128);  // (24, 32)
        sgemm_bias_kernel<<<grid, 256>>>(x, W_qkv, b_qkv, qkv, M, 3 * H_, H_);
    }

    // 2) Banded causal attention
    {
        cudaFuncSetAttribute(attn_kernel,
                             cudaFuncAttributeMaxDynamicSharedMemorySize, ATTN_SMEM);
        dim3 grid(T_ / 64, NH_, B_);         // (32, 16, 2)
        attn_kernel<<<grid, 256, ATTN_SMEM>>>(att);
    }

    // 3) Output projection: [4096,1024] @ [1024,1024] + bias
    {
        dim3 grid(H_ / 128, M / 128);        // (8, 32)
        sgemm_bias_kernel<<<grid, 256>>>(att, W_out, b_out, out, M, H_, H_);
    }
}

// round 3
// speedup vs baseline: 2.3416x; 2.3353x over previous
#include <cuda_runtime.h>
#include <math.h>
#include <stdint.h>

// Problem constants
#define B_    2
#define T_    2048
#define H_    1024
#define NH_   16
#define HD_   64
#define WIN_  256

// Scratch (device globals — allocation-free per harness rules)
__device__ float g_qkv[(size_t)B_ * T_ * 3 * H_];   // [B,T,3H]
__device__ float g_att[(size_t)B_ * T_ * H_];       // [B,T,H] attention output

// ---------------------------------------------------------------------------
// TF32 tensor-core GEMM: C[M,N] = A[M,K] @ Bm[K,N] + bias[N]
// 128x128 block tile, BK=32, 256 threads = 8 warps (2x4), warp tile 64x32.
// mma.sync.aligned.m16n8k8.row.col.f32.tf32.tf32.f32
// Inputs rounded to tf32 with cvt.rna at smem-store time (rel err ~2e-4).
// Requires M%128==0, N%128==0, K%32==0.
// ---------------------------------------------------------------------------
#define BM 128
#define BN 128
#define BK 32

__device__ __forceinline__ float f2tf32(float x) {
    uint32_t u;
    asm("cvt.rna.tf32.f32 %0, %1;" : "=r"(u) : "f"(x));
    return __uint_as_float(u);
}

__device__ __forceinline__ void mma_tf32(float c[4], const uint32_t a[4], const uint32_t b[2]) {
    asm volatile(
        "mma.sync.aligned.m16n8k8.row.col.f32.tf32.tf32.f32 "
        "{%0,%1,%2,%3}, {%4,%5,%6,%7}, {%8,%9}, {%0,%1,%2,%3};"
        : "+f"(c[0]), "+f"(c[1]), "+f"(c[2]), "+f"(c[3])
        : "r"(a[0]), "r"(a[1]), "r"(a[2]), "r"(a[3]), "r"(b[0]), "r"(b[1]));
}

__global__ __launch_bounds__(256, 2)
void gemm_tf32_bias(const float* __restrict__ A, const float* __restrict__ Bm,
                    const float* __restrict__ bias, float* __restrict__ C,
                    int M, int N, int K)
{
    __shared__ float As[BM][BK + 4];    // stride 36: conflict-free frag loads
    __shared__ float Bs[BK][BN + 8];    // stride 136: conflict-free frag loads

    const int tid  = threadIdx.x;
    const int wid  = tid >> 5;
    const int lane = tid & 31;
    const int wm   = wid >> 2;          // 0..1 (M dir)
    const int wn   = wid & 3;           // 0..3 (N dir)
    const int grp  = lane >> 2;         // 0..7
    const int qid  = lane & 3;          // 0..3

    const float* Ab = A  + (size_t)(blockIdx.y * BM) * K;
    const float* Bb = Bm + (size_t)(blockIdx.x * BN);

    float acc[4][4][4];
#pragma unroll
    for (int m = 0; m < 4; m++)
#pragma unroll
        for (int n = 0; n < 4; n++)
#pragma unroll
            for (int r = 0; r < 4; r++) acc[m][n][r] = 0.f;

    for (int k0 = 0; k0 < K; k0 += BK) {
        // Load A tile: 128x32 = 1024 float4, 4 per thread
#pragma unroll
        for (int i = 0; i < 4; i++) {
            const int flat = tid + i * 256;
            const int r  = flat >> 3;
            const int c4 = (flat & 7) * 4;
            float4 v = *(const float4*)(Ab + (size_t)r * K + k0 + c4);
            As[r][c4 + 0] = f2tf32(v.x);
            As[r][c4 + 1] = f2tf32(v.y);
            As[r][c4 + 2] = f2tf32(v.z);
            As[r][c4 + 3] = f2tf32(v.w);
        }
        // Load B tile: 32x128 = 1024 float4, 4 per thread
#pragma unroll
        for (int i = 0; i < 4; i++) {
            const int flat = tid + i * 256;
            const int r  = flat >> 5;
            const int c4 = (flat & 31) * 4;
            float4 v = *(const float4*)(Bb + (size_t)(k0 + r) * N + c4);
            Bs[r][c4 + 0] = f2tf32(v.x);
            Bs[r][c4 + 1] = f2tf32(v.y);
            Bs[r][c4 + 2] = f2tf32(v.z);
            Bs[r][c4 + 3] = f2tf32(v.w);
        }
        __syncthreads();

#pragma unroll
        for (int ks = 0; ks < BK / 8; ks++) {
            const int kb = ks * 8;
            uint32_t af[4][4], bf[4][2];
#pragma unroll
            for (int m = 0; m < 4; m++) {
                const int r = wm * 64 + m * 16;
                af[m][0] = __float_as_uint(As[r + grp    ][kb + qid    ]);
                af[m][1] = __float_as_uint(As[r + grp + 8][kb + qid    ]);
                af[m][2] = __float_as_uint(As[r + grp    ][kb + qid + 4]);
                af[m][3] = __float_as_uint(As[r + grp + 8][kb + qid + 4]);
            }
#pragma unroll
            for (int n = 0; n < 4; n++) {
                const int c = wn * 32 + n * 8 + grp;
                bf[n][0] = __float_as_uint(Bs[kb + qid    ][c]);
                bf[n][1] = __float_as_uint(Bs[kb + qid + 4][c]);
            }
#pragma unroll
            for (int m = 0; m < 4; m++)
#pragma unroll
                for (int n = 0; n < 4; n++)
                    mma_tf32(acc[m][n], af[m], bf[n]);
        }
        __syncthreads();
    }

    // Epilogue: c0,c1 at (grp, qid*2 / +1); c2,c3 at (grp+8, ...)
#pragma unroll
    for (int m = 0; m < 4; m++) {
        const int row0 = blockIdx.y * BM + wm * 64 + m * 16 + grp;
#pragma unroll
        for (int n = 0; n < 4; n++) {
            const int col = blockIdx.x * BN + wn * 32 + n * 8 + qid * 2;
            const float b0 = bias[col], b1 = bias[col + 1];
            float2 v0 = make_float2(acc[m][n][0] + b0, acc[m][n][1] + b1);
            float2 v1 = make_float2(acc[m][n][2] + b0, acc[m][n][3] + b1);
            *(float2*)(C + (size_t)row0 * N + col)       = v0;
            *(float2*)(C + (size_t)(row0 + 8) * N + col) = v1;
        }
    }
}

// ---------------------------------------------------------------------------
// Banded causal attention (flash-style online softmax). Unchanged from R1.
// Grid: (T/64, NH, B). Block: 256 threads.
// ---------------------------------------------------------------------------
#define ATTN_SMEM (3 * 64 * 65 * 4)

__global__ __launch_bounds__(256)
void attn_kernel(float* __restrict__ out)
{
    extern __shared__ float sm[];
    float* Qs  = sm;                 // [64][65]
    float* KVs = sm + 64 * 65;       // [64][65] (K, then reused for V)
    float* Ss  = sm + 2 * 64 * 65;   // [64][65] scores -> probabilities

    __shared__ float m_sm[64], l_sm[64], sc_sm[64];

    const int qt  = blockIdx.x;
    const int h   = blockIdx.y;
    const int b   = blockIdx.z;
    const int tid = threadIdx.x;
    const int tx  = tid & 15;
    const int ty  = tid >> 4;
    const int i0  = ty * 4;
    const int j0  = tx * 4;

    const size_t rowstride = 3 * H_;
    const size_t qbase = (size_t)(b * T_ + qt * 64) * rowstride + (size_t)h * HD_;

    for (int idx = tid; idx < 64 * 64; idx += 256) {
        const int i = idx >> 6, d = idx & 63;
        Qs[i * 65 + d] = g_qkv[qbase + (size_t)i * rowstride + d];
    }
    if (tid < 64) { m_sm[tid] = -1e30f; l_sm[tid] = 0.f; }

    float acc[4][4];
#pragma unroll
    for (int r = 0; r < 4; r++)
#pragma unroll
        for (int c = 0; c < 4; c++) acc[r][c] = 0.f;

    __syncthreads();

    int kt0 = qt - 4; if (kt0 < 0) kt0 = 0;

    for (int kt = kt0; kt <= qt; kt++) {
        const size_t kbase = (size_t)(b * T_ + kt * 64) * rowstride + H_ + (size_t)h * HD_;
        for (int idx = tid; idx < 64 * 64; idx += 256) {
            const int j = idx >> 6, d = idx & 63;
            KVs[j * 65 + d] = g_qkv[kbase + (size_t)j * rowstride + d];
        }
        __syncthreads();

        float s[4][4];
#pragma unroll
        for (int r = 0; r < 4; r++)
#pragma unroll
            for (int c = 0; c < 4; c++) s[r][c] = 0.f;

#pragma unroll 8
        for (int k = 0; k < 64; k++) {
            float a[4], bb[4];
#pragma unroll
            for (int r = 0; r < 4; r++) a[r]  = Qs[(i0 + r) * 65 + k];
#pragma unroll
            for (int c = 0; c < 4; c++) bb[c] = KVs[(j0 + c) * 65 + k];
#pragma unroll
            for (int r = 0; r < 4; r++)
#pragma unroll
                for (int c = 0; c < 4; c++)
                    s[r][c] = fmaf(a[r], bb[c], s[r][c]);
        }
#pragma unroll
        for (int r = 0; r < 4; r++) {
            const int ig = qt * 64 + i0 + r;
#pragma unroll
            for (int c = 0; c < 4; c++) {
                const int jg = kt * 64 + j0 + c;
                float v = s[r][c] * 0.125f;
                const int diff = ig - jg;
                if (diff < 0 || diff >= WIN_) v = -1e30f;
                Ss[(i0 + r) * 65 + j0 + c] = v;
            }
        }
        __syncthreads();

        if (tid < 64) {
            float* Sr = Ss + tid * 65;
            float mx = -1e30f;
#pragma unroll 8
            for (int j = 0; j < 64; j++) mx = fmaxf(mx, Sr[j]);
            const float mn = fmaxf(m_sm[tid], mx);
            const float sc = __expf(m_sm[tid] - mn);
            float rs = 0.f;
#pragma unroll 8
            for (int j = 0; j < 64; j++) {
                const float p = __expf(Sr[j] - mn);
                Sr[j] = p;
                rs += p;
            }
            l_sm[tid]  = l_sm[tid] * sc + rs;
            m_sm[tid]  = mn;
            sc_sm[tid] = sc;
        }
        __syncthreads();

        const size_t vbase = (size_t)(b * T_ + kt * 64) * rowstride + 2 * H_ + (size_t)h * HD_;
        for (int idx = tid; idx < 64 * 64; idx += 256) {
            const int j = idx >> 6, d = idx & 63;
            KVs[j * 65 + d] = g_qkv[vbase + (size_t)j * rowstride + d];
        }
#pragma unroll
        for (int r = 0; r < 4; r++) {
            const float sc = sc_sm[i0 + r];
#pragma unroll
            for (int c = 0; c < 4; c++) acc[r][c] *= sc;
        }
        __syncthreads();

#pragma unroll 8
        for (int k = 0; k < 64; k++) {
            float p[4], vv[4];
#pragma unroll
            for (int r = 0; r < 4; r++) p[r]  = Ss[(i0 + r) * 65 + k];
#pragma unroll
            for (int c = 0; c < 4; c++) vv[c] = KVs[k * 65 + j0 + c];
#pragma unroll
            for (int r = 0; r < 4; r++)
#pragma unroll
                for (int c = 0; c < 4; c++)
                    acc[r][c] = fmaf(p[r], vv[c], acc[r][c]);
        }
        __syncthreads();
    }

#pragma unroll
    for (int r = 0; r < 4; r++) {
        const float inv = 1.f / l_sm[i0 + r];
        const int trow = qt * 64 + i0 + r;
        float* op = out + (size_t)(b * T_ + trow) * H_ + (size_t)h * HD_ + j0;
#pragma unroll
        for (int c = 0; c < 4; c++) op[c] = acc[r][c] * inv;
    }
}

// ---------------------------------------------------------------------------
// Launch: qkv GEMM -> banded attention -> out GEMM
// ---------------------------------------------------------------------------
extern "C" void kernel_launch(void* const* d_in, const int* in_sizes, int n_in,
                              void* d_out, int out_size)
{
    const float* x     = (const float*)d_in[0];   // [B,T,H]
    const float* W_qkv = (const float*)d_in[1];   // [H,3H]
    const float* b_qkv = (const float*)d_in[2];   // [3H]
    const float* W_out = (const float*)d_in[3];   // [H,H]
    const float* b_out = (const float*)d_in[4];   // [H]
    float* out = (float*)d_out;                   // [B,T,H]

    float* qkv; cudaGetSymbolAddress((void**)&qkv, g_qkv);
    float* att; cudaGetSymbolAddress((void**)&att, g_att);

    const int M = B_ * T_;   // 4096

    // 1) QKV projection: [4096,1024] @ [1024,3072] + bias  (tf32 tensor cores)
    {
        dim3 grid((3 * H_) / BN, M / BM);    // (24, 32)
        gemm_tf32_bias<<<grid, 256>>>(x, W_qkv, b_qkv, qkv, M, 3 * H_, H_);
    }

    // 2) Banded causal attention
    {
        cudaFuncSetAttribute(attn_kernel,
                             cudaFuncAttributeMaxDynamicSharedMemorySize, ATTN_SMEM);
        dim3 grid(T_ / 64, NH_, B_);         // (32, 16, 2)
        attn_kernel<<<grid, 256, ATTN_SMEM>>>(att);
    }

    // 3) Output projection: [4096,1024] @ [1024,1024] + bias  (tf32 tensor cores)
    {
        dim3 grid(H_ / BN, M / BM);          // (8, 32)
        gemm_tf32_bias<<<grid, 256>>>(att, W_out, b_out, out, M, H_, H_);
    }
}

// round 4
// speedup vs baseline: 3.3573x; 1.4338x over previous
#include <cuda_runtime.h>
#include <math.h>
#include <stdint.h>

// Problem constants
#define B_    2
#define T_    2048
#define H_    1024
#define NH_   16
#define HD_   64
#define WIN_  256

// Scratch (device globals — allocation-free per harness rules)
__device__ float g_qkv[(size_t)B_ * T_ * 3 * H_];   // [B,T,3H]
__device__ float g_att[(size_t)B_ * T_ * H_];       // [B,T,H] attention output

__device__ __forceinline__ float f2tf32(float x) {
    uint32_t u;
    asm("cvt.rna.tf32.f32 %0, %1;" : "=r"(u) : "f"(x));
    return __uint_as_float(u);
}

__device__ __forceinline__ void mma_tf32(float c[4], const uint32_t a[4], const uint32_t b[2]) {
    asm volatile(
        "mma.sync.aligned.m16n8k8.row.col.f32.tf32.tf32.f32 "
        "{%0,%1,%2,%3}, {%4,%5,%6,%7}, {%8,%9}, {%0,%1,%2,%3};"
        : "+f"(c[0]), "+f"(c[1]), "+f"(c[2]), "+f"(c[3])
        : "r"(a[0]), "r"(a[1]), "r"(a[2]), "r"(a[3]), "r"(b[0]), "r"(b[1]));
}

// ---------------------------------------------------------------------------
// TF32 tensor-core GEMM: C[M,N] = A[M,K] @ Bm[K,N] + bias[N]  (unchanged R2)
// ---------------------------------------------------------------------------
#define BM 128
#define BN 128
#define BK 32

__global__ __launch_bounds__(256, 2)
void gemm_tf32_bias(const float* __restrict__ A, const float* __restrict__ Bm,
                    const float* __restrict__ bias, float* __restrict__ C,
                    int M, int N, int K)
{
    __shared__ float As[BM][BK + 4];
    __shared__ float Bs[BK][BN + 8];

    const int tid  = threadIdx.x;
    const int wid  = tid >> 5;
    const int lane = tid & 31;
    const int wm   = wid >> 2;
    const int wn   = wid & 3;
    const int grp  = lane >> 2;
    const int qid  = lane & 3;

    const float* Ab = A  + (size_t)(blockIdx.y * BM) * K;
    const float* Bb = Bm + (size_t)(blockIdx.x * BN);

    float acc[4][4][4];
#pragma unroll
    for (int m = 0; m < 4; m++)
#pragma unroll
        for (int n = 0; n < 4; n++)
#pragma unroll
            for (int r = 0; r < 4; r++) acc[m][n][r] = 0.f;

    for (int k0 = 0; k0 < K; k0 += BK) {
#pragma unroll
        for (int i = 0; i < 4; i++) {
            const int flat = tid + i * 256;
            const int r  = flat >> 3;
            const int c4 = (flat & 7) * 4;
            float4 v = *(const float4*)(Ab + (size_t)r * K + k0 + c4);
            As[r][c4 + 0] = f2tf32(v.x);
            As[r][c4 + 1] = f2tf32(v.y);
            As[r][c4 + 2] = f2tf32(v.z);
            As[r][c4 + 3] = f2tf32(v.w);
        }
#pragma unroll
        for (int i = 0; i < 4; i++) {
            const int flat = tid + i * 256;
            const int r  = flat >> 5;
            const int c4 = (flat & 31) * 4;
            float4 v = *(const float4*)(Bb + (size_t)(k0 + r) * N + c4);
            Bs[r][c4 + 0] = f2tf32(v.x);
            Bs[r][c4 + 1] = f2tf32(v.y);
            Bs[r][c4 + 2] = f2tf32(v.z);
            Bs[r][c4 + 3] = f2tf32(v.w);
        }
        __syncthreads();

#pragma unroll
        for (int ks = 0; ks < BK / 8; ks++) {
            const int kb = ks * 8;
            uint32_t af[4][4], bf[4][2];
#pragma unroll
            for (int m = 0; m < 4; m++) {
                const int r = wm * 64 + m * 16;
                af[m][0] = __float_as_uint(As[r + grp    ][kb + qid    ]);
                af[m][1] = __float_as_uint(As[r + grp + 8][kb + qid    ]);
                af[m][2] = __float_as_uint(As[r + grp    ][kb + qid + 4]);
                af[m][3] = __float_as_uint(As[r + grp + 8][kb + qid + 4]);
            }
#pragma unroll
            for (int n = 0; n < 4; n++) {
                const int c = wn * 32 + n * 8 + grp;
                bf[n][0] = __float_as_uint(Bs[kb + qid    ][c]);
                bf[n][1] = __float_as_uint(Bs[kb + qid + 4][c]);
            }
#pragma unroll
            for (int m = 0; m < 4; m++)
#pragma unroll
                for (int n = 0; n < 4; n++)
                    mma_tf32(acc[m][n], af[m], bf[n]);
        }
        __syncthreads();
    }

#pragma unroll
    for (int m = 0; m < 4; m++) {
        const int row0 = blockIdx.y * BM + wm * 64 + m * 16 + grp;
#pragma unroll
        for (int n = 0; n < 4; n++) {
            const int col = blockIdx.x * BN + wn * 32 + n * 8 + qid * 2;
            const float b0 = bias[col], b1 = bias[col + 1];
            float2 v0 = make_float2(acc[m][n][0] + b0, acc[m][n][1] + b1);
            float2 v1 = make_float2(acc[m][n][2] + b0, acc[m][n][3] + b1);
            *(float2*)(C + (size_t)row0 * N + col)       = v0;
            *(float2*)(C + (size_t)(row0 + 8) * N + col) = v1;
        }
    }
}

// ---------------------------------------------------------------------------
// Banded causal attention on tensor cores (tf32 mma, flash online softmax).
// Block: 128 threads (4 warps). Each warp: 16 query rows x 64 cols.
// Grid: (T/64, NH, B).
// smem: Qs[64][68], Ps[64][68], Ks[64][68], Vs[64][72]  = 70,656 B dynamic.
// Strides chosen for conflict-free mma fragment loads:
//   A-operand arrays (Qs, Ps): stride 68 -> bank = 4g + q  (bijective)
//   Ks as S-mma B operand read [j][d]:    bank = 4g + q
//   Vs as O-mma B operand read [j][d]: stride 72 -> bank = 8q + g
// ---------------------------------------------------------------------------
#define ATTN_SMEM2 ((64*68*3 + 64*72) * 4)

__global__ __launch_bounds__(128)
void attn_mma_kernel(float* __restrict__ out)
{
    extern __shared__ float sm[];
    float* Qs = sm;                   // [64][68]
    float* Ps = Qs + 64 * 68;         // [64][68]
    float* Ks = Ps + 64 * 68;         // [64][68]
    float* Vs = Ks + 64 * 68;         // [64][72]

    const int qt  = blockIdx.x;
    const int h   = blockIdx.y;
    const int b   = blockIdx.z;
    const int tid = threadIdx.x;
    const int wid  = tid >> 5;
    const int lane = tid & 31;
    const int g = lane >> 2;          // 0..7
    const int q = lane & 3;           // 0..3
    const int r0 = wid * 16;          // warp row base

    const size_t rs = 3 * H_;
    const size_t base_bt = (size_t)b * T_ * rs + (size_t)h * HD_;
    const size_t qbase = base_bt + (size_t)(qt * 64) * rs;

    // Load Q tile, pre-scaled by 1/sqrt(64)=0.125 (exact), tf32-rounded.
#pragma unroll
    for (int it = 0; it < 8; it++) {
        const int idx = tid + it * 128;          // 0..1023 float4s
        const int i = idx >> 4, d4 = (idx & 15) << 2;
        float4 v = *(const float4*)&g_qkv[qbase + (size_t)i * rs + d4];
        float4 w;
        w.x = f2tf32(v.x * 0.125f);
        w.y = f2tf32(v.y * 0.125f);
        w.z = f2tf32(v.z * 0.125f);
        w.w = f2tf32(v.w * 0.125f);
        *(float4*)&Qs[i * 68 + d4] = w;
    }

    float oc[8][4];
#pragma unroll
    for (int nt = 0; nt < 8; nt++)
#pragma unroll
        for (int r = 0; r < 4; r++) oc[nt][r] = 0.f;

    float m0 = -1e30f, m1 = -1e30f, l0 = 0.f, l1 = 0.f;

    int kt0 = qt - 4; if (kt0 < 0) kt0 = 0;

    for (int kt = kt0; kt <= qt; kt++) {
        __syncthreads();   // prior iter done reading Ks/Vs/Ps (1st iter: Q stores ordered by next sync)

        const size_t kbase = base_bt + (size_t)(kt * 64) * rs + H_;
#pragma unroll
        for (int it = 0; it < 8; it++) {
            const int idx = tid + it * 128;
            const int j = idx >> 4, d4 = (idx & 15) << 2;
            float4 kv = *(const float4*)&g_qkv[kbase + (size_t)j * rs + d4];
            float4 vv = *(const float4*)&g_qkv[kbase + H_ + (size_t)j * rs + d4];
            float4 kw, vw;
            kw.x = f2tf32(kv.x); kw.y = f2tf32(kv.y); kw.z = f2tf32(kv.z); kw.w = f2tf32(kv.w);
            vw.x = f2tf32(vv.x); vw.y = f2tf32(vv.y); vw.z = f2tf32(vv.z); vw.w = f2tf32(vv.w);
            *(float4*)&Ks[j * 68 + d4] = kw;
            *(float4*)&Vs[j * 72 + d4] = vw;
        }
        __syncthreads();

        // ---- S = Q @ K^T  (warp rows r0..r0+15, all 64 cols) ----
        float s[8][4];
#pragma unroll
        for (int nt = 0; nt < 8; nt++)
#pragma unroll
            for (int r = 0; r < 4; r++) s[nt][r] = 0.f;

#pragma unroll
        for (int ks = 0; ks < 8; ks++) {
            const int kb = ks * 8;
            uint32_t a[4];
            a[0] = __float_as_uint(Qs[(r0 + g    ) * 68 + kb + q    ]);
            a[1] = __float_as_uint(Qs[(r0 + g + 8) * 68 + kb + q    ]);
            a[2] = __float_as_uint(Qs[(r0 + g    ) * 68 + kb + q + 4]);
            a[3] = __float_as_uint(Qs[(r0 + g + 8) * 68 + kb + q + 4]);
#pragma unroll
            for (int nt = 0; nt < 8; nt++) {
                uint32_t bb[2];
                bb[0] = __float_as_uint(Ks[(nt * 8 + g) * 68 + kb + q    ]);
                bb[1] = __float_as_uint(Ks[(nt * 8 + g) * 68 + kb + q + 4]);
                mma_tf32(s[nt], a, bb);
            }
        }

        // ---- mask + warp-local online softmax ----
        const int ig0 = qt * 64 + r0 + g;   // rows for regs 0,1
        const int ig1 = ig0 + 8;            // rows for regs 2,3
#pragma unroll
        for (int nt = 0; nt < 8; nt++) {
            const int jg = kt * 64 + nt * 8 + 2 * q;
            int d00 = ig0 - jg;     if (d00 < 0 || d00 >= WIN_) s[nt][0] = -1e30f;
            int d01 = ig0 - jg - 1; if (d01 < 0 || d01 >= WIN_) s[nt][1] = -1e30f;
            int d10 = ig1 - jg;     if (d10 < 0 || d10 >= WIN_) s[nt][2] = -1e30f;
            int d11 = ig1 - jg - 1; if (d11 < 0 || d11 >= WIN_) s[nt][3] = -1e30f;
        }
        float mx0 = -1e30f, mx1 = -1e30f;
#pragma unroll
        for (int nt = 0; nt < 8; nt++) {
            mx0 = fmaxf(mx0, fmaxf(s[nt][0], s[nt][1]));
            mx1 = fmaxf(mx1, fmaxf(s[nt][2], s[nt][3]));
        }
        mx0 = fmaxf(mx0, __shfl_xor_sync(0xffffffffu, mx0, 1));
        mx0 = fmaxf(mx0, __shfl_xor_sync(0xffffffffu, mx0, 2));
        mx1 = fmaxf(mx1, __shfl_xor_sync(0xffffffffu, mx1, 1));
        mx1 = fmaxf(mx1, __shfl_xor_sync(0xffffffffu, mx1, 2));

        const float mn0 = fmaxf(m0, mx0), mn1 = fmaxf(m1, mx1);
        const float e0 = __expf(m0 - mn0), e1 = __expf(m1 - mn1);
        float rs0 = 0.f, rs1 = 0.f;
#pragma unroll
        for (int nt = 0; nt < 8; nt++) {
            const float p00 = __expf(s[nt][0] - mn0);
            const float p01 = __expf(s[nt][1] - mn0);
            const float p10 = __expf(s[nt][2] - mn1);
            const float p11 = __expf(s[nt][3] - mn1);
            rs0 += p00 + p01;
            rs1 += p10 + p11;
            float2 v0 = make_float2(f2tf32(p00), f2tf32(p01));
            float2 v1 = make_float2(f2tf32(p10), f2tf32(p11));
            *(float2*)&Ps[(r0 + g    ) * 68 + nt * 8 + 2 * q] = v0;
            *(float2*)&Ps[(r0 + g + 8) * 68 + nt * 8 + 2 * q] = v1;
        }
        rs0 += __shfl_xor_sync(0xffffffffu, rs0, 1);
        rs0 += __shfl_xor_sync(0xffffffffu, rs0, 2);
        rs1 += __shfl_xor_sync(0xffffffffu, rs1, 1);
        rs1 += __shfl_xor_sync(0xffffffffu, rs1, 2);

        l0 = l0 * e0 + rs0;  m0 = mn0;
        l1 = l1 * e1 + rs1;  m1 = mn1;

#pragma unroll
        for (int nt = 0; nt < 8; nt++) {
            oc[nt][0] *= e0; oc[nt][1] *= e0;
            oc[nt][2] *= e1; oc[nt][3] *= e1;
        }
        __syncthreads();   // Ps visible to all warps of... (warp-local, but also orders vs next-iter overwrite)

        // ---- O += P @ V ----
#pragma unroll
        for (int ks = 0; ks < 8; ks++) {
            const int kb = ks * 8;
            uint32_t a[4];
            a[0] = __float_as_uint(Ps[(r0 + g    ) * 68 + kb + q    ]);
            a[1] = __float_as_uint(Ps[(r0 + g + 8) * 68 + kb + q    ]);
            a[2] = __float_as_uint(Ps[(r0 + g    ) * 68 + kb + q + 4]);
            a[3] = __float_as_uint(Ps[(r0 + g + 8) * 68 + kb + q + 4]);
#pragma unroll
            for (int nt = 0; nt < 8; nt++) {
                uint32_t bb[2];
                bb[0] = __float_as_uint(Vs[(kb + q    ) * 72 + nt * 8 + g]);
                bb[1] = __float_as_uint(Vs[(kb + q + 4) * 72 + nt * 8 + g]);
                mma_tf32(oc[nt], a, bb);
            }
        }
    }

    // ---- normalize + write out[b][row][h*64 + d] ----
    const float inv0 = 1.f / l0, inv1 = 1.f / l1;
    const int row0g = qt * 64 + r0 + g;
#pragma unroll
    for (int nt = 0; nt < 8; nt++) {
        const int col = h * HD_ + nt * 8 + 2 * q;
        float2 v0 = make_float2(oc[nt][0] * inv0, oc[nt][1] * inv0);
        float2 v1 = make_float2(oc[nt][2] * inv1, oc[nt][3] * inv1);
        *(float2*)&out[(size_t)(b * T_ + row0g    ) * H_ + col] = v0;
        *(float2*)&out[(size_t)(b * T_ + row0g + 8) * H_ + col] = v1;
    }
}

// ---------------------------------------------------------------------------
// Launch: qkv GEMM -> banded attention (mma) -> out GEMM
// ---------------------------------------------------------------------------
extern "C" void kernel_launch(void* const* d_in, const int* in_sizes, int n_in,
                              void* d_out, int out_size)
{
    const float* x     = (const float*)d_in[0];
    const float* W_qkv = (const float*)d_in[1];
    const float* b_qkv = (const float*)d_in[2];
    const float* W_out = (const float*)d_in[3];
    const float* b_out = (const float*)d_in[4];
    float* out = (float*)d_out;

    float* qkv; cudaGetSymbolAddress((void**)&qkv, g_qkv);
    float* att; cudaGetSymbolAddress((void**)&att, g_att);

    const int M = B_ * T_;

    {
        dim3 grid((3 * H_) / BN, M / BM);
        gemm_tf32_bias<<<grid, 256>>>(x, W_qkv, b_qkv, qkv, M, 3 * H_, H_);
    }
    {
        cudaFuncSetAttribute(attn_mma_kernel,
                             cudaFuncAttributeMaxDynamicSharedMemorySize, ATTN_SMEM2);
        dim3 grid(T_ / 64, NH_, B_);
        attn_mma_kernel<<<grid, 128, ATTN_SMEM2>>>(att);
    }
    {
        dim3 grid(H_ / BN, M / BM);
        gemm_tf32_bias<<<grid, 256>>>(att, W_out, b_out, out, M, H_, H_);
    }
}

// round 5
// speedup vs baseline: 3.5985x; 1.0718x over previous
#include <cuda_runtime.h>
#include <math.h>
#include <stdint.h>

// Problem constants
#define B_    2
#define T_    2048
#define H_    1024
#define NH_   16
#define HD_   64
#define WIN_  256

// Scratch (device globals — allocation-free per harness rules)
__device__ float g_qkv[(size_t)B_ * T_ * 3 * H_];   // [B,T,3H]
__device__ float g_att[(size_t)B_ * T_ * H_];       // [B,T,H] attention output

__device__ __forceinline__ float f2tf32(float x) {
    uint32_t u;
    asm("cvt.rna.tf32.f32 %0, %1;" : "=r"(u) : "f"(x));
    return __uint_as_float(u);
}

__device__ __forceinline__ uint32_t ld_tf32(const float* p) {
    uint32_t u;
    asm("cvt.rna.tf32.f32 %0, %1;" : "=r"(u) : "f"(*p));
    return u;
}

__device__ __forceinline__ void mma_tf32(float c[4], const uint32_t a[4], const uint32_t b[2]) {
    asm volatile(
        "mma.sync.aligned.m16n8k8.row.col.f32.tf32.tf32.f32 "
        "{%0,%1,%2,%3}, {%4,%5,%6,%7}, {%8,%9}, {%0,%1,%2,%3};"
        : "+f"(c[0]), "+f"(c[1]), "+f"(c[2]), "+f"(c[3])
        : "r"(a[0]), "r"(a[1]), "r"(a[2]), "r"(a[3]), "r"(b[0]), "r"(b[1]));
}

__device__ __forceinline__ void cp_async16(float* smem_dst, const float* gsrc) {
    uint32_t s = (uint32_t)__cvta_generic_to_shared(smem_dst);
    asm volatile("cp.async.cg.shared.global [%0], [%1], 16;" :: "r"(s), "l"(gsrc));
}
__device__ __forceinline__ void cp_commit() {
    asm volatile("cp.async.commit_group;");
}
template <int N>
__device__ __forceinline__ void cp_wait() {
    asm volatile("cp.async.wait_group %0;" :: "n"(N));
}

// ---------------------------------------------------------------------------
// TF32 tensor-core GEMM with cp.async double buffering.
// C[M,N] = A[M,K] @ Bm[K,N] + bias[N]
// 128x128 block tile, BK=32, 256 threads = 8 warps (2x4), warp tile 64x32.
// Raw fp32 staged in smem via LDGSTS; tf32 cvt applied at fragment load.
// A stride 36, B stride 136 (conflict-free fragment access).
// ---------------------------------------------------------------------------
#define BM 128
#define BN 128
#define BK 32
#define AS_STRIDE 36
#define BS_STRIDE 136
#define STAGE_FLOATS (BM * AS_STRIDE + BK * BS_STRIDE)   // 4608 + 4352 = 8960
#define GEMM_SMEM (2 * STAGE_FLOATS * 4)                 // 71680 B

__global__ __launch_bounds__(256, 2)
void gemm_tf32_bias(const float* __restrict__ A, const float* __restrict__ Bm,
                    const float* __restrict__ bias, float* __restrict__ C,
                    int M, int N, int K)
{
    extern __shared__ float smem[];
    // stage s: As = smem + s*STAGE_FLOATS, Bs = As + BM*AS_STRIDE

    const int tid  = threadIdx.x;
    const int wid  = tid >> 5;
    const int lane = tid & 31;
    const int wm   = wid >> 2;          // 0..1 (M dir)
    const int wn   = wid & 3;           // 0..3 (N dir)
    const int grp  = lane >> 2;         // 0..7
    const int qid  = lane & 3;          // 0..3

    const float* Ab = A  + (size_t)(blockIdx.y * BM) * K;
    const float* Bb = Bm + (size_t)(blockIdx.x * BN);

    // per-thread copy coordinates
    const int aRow0 = tid >> 3;          // row for i-th A float4: aRow0 + i*? -- we use flat
    float acc[4][4][4];
#pragma unroll
    for (int m = 0; m < 4; m++)
#pragma unroll
        for (int n = 0; n < 4; n++)
#pragma unroll
            for (int r = 0; r < 4; r++) acc[m][n][r] = 0.f;

    const int ITER = K / BK;

    // ---- stage loader ----
    auto load_stage = [&](int k0, int s) {
        float* As = smem + s * STAGE_FLOATS;
        float* Bs = As + BM * AS_STRIDE;
#pragma unroll
        for (int i = 0; i < 4; i++) {
            const int flat = tid + i * 256;          // 0..1023
            const int r  = flat >> 3;                // 0..127
            const int c4 = (flat & 7) * 4;           // 0..28
            cp_async16(As + r * AS_STRIDE + c4, Ab + (size_t)r * K + k0 + c4);
        }
#pragma unroll
        for (int i = 0; i < 4; i++) {
            const int flat = tid + i * 256;
            const int r  = flat >> 5;                // 0..31
            const int c4 = (flat & 31) * 4;          // 0..124
            cp_async16(Bs + r * BS_STRIDE + c4, Bb + (size_t)(k0 + r) * N + c4);
        }
        cp_commit();
    };
    (void)aRow0;

    load_stage(0, 0);

    for (int it = 0; it < ITER; it++) {
        if (it + 1 < ITER) {
            load_stage((it + 1) * BK, (it + 1) & 1);
            cp_wait<1>();
        } else {
            cp_wait<0>();
        }
        __syncthreads();

        const float* As = smem + (it & 1) * STAGE_FLOATS;
        const float* Bs = As + BM * AS_STRIDE;

#pragma unroll
        for (int ks = 0; ks < BK / 8; ks++) {
            const int kb = ks * 8;
            uint32_t af[4][4], bf[4][2];
#pragma unroll
            for (int m = 0; m < 4; m++) {
                const int r = wm * 64 + m * 16;
                af[m][0] = ld_tf32(As + (r + grp    ) * AS_STRIDE + kb + qid    );
                af[m][1] = ld_tf32(As + (r + grp + 8) * AS_STRIDE + kb + qid    );
                af[m][2] = ld_tf32(As + (r + grp    ) * AS_STRIDE + kb + qid + 4);
                af[m][3] = ld_tf32(As + (r + grp + 8) * AS_STRIDE + kb + qid + 4);
            }
#pragma unroll
            for (int n = 0; n < 4; n++) {
                const int c = wn * 32 + n * 8 + grp;
                bf[n][0] = ld_tf32(Bs + (kb + qid    ) * BS_STRIDE + c);
                bf[n][1] = ld_tf32(Bs + (kb + qid + 4) * BS_STRIDE + c);
            }
#pragma unroll
            for (int m = 0; m < 4; m++)
#pragma unroll
                for (int n = 0; n < 4; n++)
                    mma_tf32(acc[m][n], af[m], bf[n]);
        }
        __syncthreads();   // all reads done before stage (it+2)&1 == (it&1) overwrite
    }

    // Epilogue with bias
#pragma unroll
    for (int m = 0; m < 4; m++) {
        const int row0 = blockIdx.y * BM + wm * 64 + m * 16 + grp;
#pragma unroll
        for (int n = 0; n < 4; n++) {
            const int col = blockIdx.x * BN + wn * 32 + n * 8 + qid * 2;
            const float b0 = bias[col], b1 = bias[col + 1];
            float2 v0 = make_float2(acc[m][n][0] + b0, acc[m][n][1] + b1);
            float2 v1 = make_float2(acc[m][n][2] + b0, acc[m][n][3] + b1);
            *(float2*)(C + (size_t)row0 * N + col)       = v0;
            *(float2*)(C + (size_t)(row0 + 8) * N + col) = v1;
        }
    }
}

// ---------------------------------------------------------------------------
// Banded causal attention on tensor cores (tf32 mma, flash online softmax).
// Unchanged from R3 (58us, passing).
// ---------------------------------------------------------------------------
#define ATTN_SMEM2 ((64*68*3 + 64*72) * 4)

__global__ __launch_bounds__(128)
void attn_mma_kernel(float* __restrict__ out)
{
    extern __shared__ float sm[];
    float* Qs = sm;                   // [64][68]
    float* Ps = Qs + 64 * 68;         // [64][68]
    float* Ks = Ps + 64 * 68;         // [64][68]
    float* Vs = Ks + 64 * 68;         // [64][72]

    const int qt  = blockIdx.x;
    const int h   = blockIdx.y;
    const int b   = blockIdx.z;
    const int tid = threadIdx.x;
    const int wid  = tid >> 5;
    const int lane = tid & 31;
    const int g = lane >> 2;
    const int q = lane & 3;
    const int r0 = wid * 16;

    const size_t rs = 3 * H_;
    const size_t base_bt = (size_t)b * T_ * rs + (size_t)h * HD_;
    const size_t qbase = base_bt + (size_t)(qt * 64) * rs;

#pragma unroll
    for (int it = 0; it < 8; it++) {
        const int idx = tid + it * 128;
        const int i = idx >> 4, d4 = (idx & 15) << 2;
        float4 v = *(const float4*)&g_qkv[qbase + (size_t)i * rs + d4];
        float4 w;
        w.x = f2tf32(v.x * 0.125f);
        w.y = f2tf32(v.y * 0.125f);
        w.z = f2tf32(v.z * 0.125f);
        w.w = f2tf32(v.w * 0.125f);
        *(float4*)&Qs[i * 68 + d4] = w;
    }

    float oc[8][4];
#pragma unroll
    for (int nt = 0; nt < 8; nt++)
#pragma unroll
        for (int r = 0; r < 4; r++) oc[nt][r] = 0.f;

    float m0 = -1e30f, m1 = -1e30f, l0 = 0.f, l1 = 0.f;

    int kt0 = qt - 4; if (kt0 < 0) kt0 = 0;

    for (int kt = kt0; kt <= qt; kt++) {
        __syncthreads();

        const size_t kbase = base_bt + (size_t)(kt * 64) * rs + H_;
#pragma unroll
        for (int it = 0; it < 8; it++) {
            const int idx = tid + it * 128;
            const int j = idx >> 4, d4 = (idx & 15) << 2;
            float4 kv = *(const float4*)&g_qkv[kbase + (size_t)j * rs + d4];
            float4 vv = *(const float4*)&g_qkv[kbase + H_ + (size_t)j * rs + d4];
            float4 kw, vw;
            kw.x = f2tf32(kv.x); kw.y = f2tf32(kv.y); kw.z = f2tf32(kv.z); kw.w = f2tf32(kv.w);
            vw.x = f2tf32(vv.x); vw.y = f2tf32(vv.y); vw.z = f2tf32(vv.z); vw.w = f2tf32(vv.w);
            *(float4*)&Ks[j * 68 + d4] = kw;
            *(float4*)&Vs[j * 72 + d4] = vw;
        }
        __syncthreads();

        float s[8][4];
#pragma unroll
        for (int nt = 0; nt < 8; nt++)
#pragma unroll
            for (int r = 0; r < 4; r++) s[nt][r] = 0.f;

#pragma unroll
        for (int ks = 0; ks < 8; ks++) {
            const int kb = ks * 8;
            uint32_t a[4];
            a[0] = __float_as_uint(Qs[(r0 + g    ) * 68 + kb + q    ]);
            a[1] = __float_as_uint(Qs[(r0 + g + 8) * 68 + kb + q    ]);
            a[2] = __float_as_uint(Qs[(r0 + g    ) * 68 + kb + q + 4]);
            a[3] = __float_as_uint(Qs[(r0 + g + 8) * 68 + kb + q + 4]);
#pragma unroll
            for (int nt = 0; nt < 8; nt++) {
                uint32_t bb[2];
                bb[0] = __float_as_uint(Ks[(nt * 8 + g) * 68 + kb + q    ]);
                bb[1] = __float_as_uint(Ks[(nt * 8 + g) * 68 + kb + q + 4]);
                mma_tf32(s[nt], a, bb);
            }
        }

        const int ig0 = qt * 64 + r0 + g;
        const int ig1 = ig0 + 8;
#pragma unroll
        for (int nt = 0; nt < 8; nt++) {
            const int jg = kt * 64 + nt * 8 + 2 * q;
            int d00 = ig0 - jg;     if (d00 < 0 || d00 >= WIN_) s[nt][0] = -1e30f;
            int d01 = ig0 - jg - 1; if (d01 < 0 || d01 >= WIN_) s[nt][1] = -1e30f;
            int d10 = ig1 - jg;     if (d10 < 0 || d10 >= WIN_) s[nt][2] = -1e30f;
            int d11 = ig1 - jg - 1; if (d11 < 0 || d11 >= WIN_) s[nt][3] = -1e30f;
        }
        float mx0 = -1e30f, mx1 = -1e30f;
#pragma unroll
        for (int nt = 0; nt < 8; nt++) {
            mx0 = fmaxf(mx0, fmaxf(s[nt][0], s[nt][1]));
            mx1 = fmaxf(mx1, fmaxf(s[nt][2], s[nt][3]));
        }
        mx0 = fmaxf(mx0, __shfl_xor_sync(0xffffffffu, mx0, 1));
        mx0 = fmaxf(mx0, __shfl_xor_sync(0xffffffffu, mx0, 2));
        mx1 = fmaxf(mx1, __shfl_xor_sync(0xffffffffu, mx1, 1));
        mx1 = fmaxf(mx1, __shfl_xor_sync(0xffffffffu, mx1, 2));

        const float mn0 = fmaxf(m0, mx0), mn1 = fmaxf(m1, mx1);
        const float e0 = __expf(m0 - mn0), e1 = __expf(m1 - mn1);
        float rs0 = 0.f, rs1 = 0.f;
#pragma unroll
        for (int nt = 0; nt < 8; nt++) {
            const float p00 = __expf(s[nt][0] - mn0);
            const float p01 = __expf(s[nt][1] - mn0);
            const float p10 = __expf(s[nt][2] - mn1);
            const float p11 = __expf(s[nt][3] - mn1);
            rs0 += p00 + p01;
            rs1 += p10 + p11;
            float2 v0 = make_float2(f2tf32(p00), f2tf32(p01));
            float2 v1 = make_float2(f2tf32(p10), f2tf32(p11));
            *(float2*)&Ps[(r0 + g    ) * 68 + nt * 8 + 2 * q] = v0;
            *(float2*)&Ps[(r0 + g + 8) * 68 + nt * 8 + 2 * q] = v1;
        }
        rs0 += __shfl_xor_sync(0xffffffffu, rs0, 1);
        rs0 += __shfl_xor_sync(0xffffffffu, rs0, 2);
        rs1 += __shfl_xor_sync(0xffffffffu, rs1, 1);
        rs1 += __shfl_xor_sync(0xffffffffu, rs1, 2);

        l0 = l0 * e0 + rs0;  m0 = mn0;
        l1 = l1 * e1 + rs1;  m1 = mn1;

#pragma unroll
        for (int nt = 0; nt < 8; nt++) {
            oc[nt][0] *= e0; oc[nt][1] *= e0;
            oc[nt][2] *= e1; oc[nt][3] *= e1;
        }
        __syncthreads();

#pragma unroll
        for (int ks = 0; ks < 8; ks++) {
            const int kb = ks * 8;
            uint32_t a[4];
            a[0] = __float_as_uint(Ps[(r0 + g    ) * 68 + kb + q    ]);
            a[1] = __float_as_uint(Ps[(r0 + g + 8) * 68 + kb + q    ]);
            a[2] = __float_as_uint(Ps[(r0 + g    ) * 68 + kb + q + 4]);
            a[3] = __float_as_uint(Ps[(r0 + g + 8) * 68 + kb + q + 4]);
#pragma unroll
            for (int nt = 0; nt < 8; nt++) {
                uint32_t bb[2];
                bb[0] = __float_as_uint(Vs[(kb + q    ) * 72 + nt * 8 + g]);
                bb[1] = __float_as_uint(Vs[(kb + q + 4) * 72 + nt * 8 + g]);
                mma_tf32(oc[nt], a, bb);
            }
        }
    }

    const float inv0 = 1.f / l0, inv1 = 1.f / l1;
    const int row0g = qt * 64 + r0 + g;
#pragma unroll
    for (int nt = 0; nt < 8; nt++) {
        const int col = h * HD_ + nt * 8 + 2 * q;
        float2 v0 = make_float2(oc[nt][0] * inv0, oc[nt][1] * inv0);
        float2 v1 = make_float2(oc[nt][2] * inv1, oc[nt][3] * inv1);
        *(float2*)&out[(size_t)(b * T_ + row0g    ) * H_ + col] = v0;
        *(float2*)&out[(size_t)(b * T_ + row0g + 8) * H_ + col] = v1;
    }
}

// ---------------------------------------------------------------------------
// Launch: qkv GEMM -> banded attention (mma) -> out GEMM
// ---------------------------------------------------------------------------
extern "C" void kernel_launch(void* const* d_in, const int* in_sizes, int n_in,
                              void* d_out, int out_size)
{
    const float* x     = (const float*)d_in[0];
    const float* W_qkv = (const float*)d_in[1];
    const float* b_qkv = (const float*)d_in[2];
    const float* W_out = (const float*)d_in[3];
    const float* b_out = (const float*)d_in[4];
    float* out = (float*)d_out;

    float* qkv; cudaGetSymbolAddress((void**)&qkv, g_qkv);
    float* att; cudaGetSymbolAddress((void**)&att, g_att);

    const int M = B_ * T_;

    cudaFuncSetAttribute(gemm_tf32_bias,
                         cudaFuncAttributeMaxDynamicSharedMemorySize, GEMM_SMEM);
    {
        dim3 grid((3 * H_) / BN, M / BM);
        gemm_tf32_bias<<<grid, 256, GEMM_SMEM>>>(x, W_qkv, b_qkv, qkv, M, 3 * H_, H_);
    }
    {
        cudaFuncSetAttribute(attn_mma_kernel,
                             cudaFuncAttributeMaxDynamicSharedMemorySize, ATTN_SMEM2);
        dim3 grid(T_ / 64, NH_, B_);
        attn_mma_kernel<<<grid, 128, ATTN_SMEM2>>>(att);
    }
    {
        dim3 grid(H_ / BN, M / BM);
        gemm_tf32_bias<<<grid, 256, GEMM_SMEM>>>(att, W_out, b_out, out, M, H_, H_);
    }
}

// round 6
// speedup vs baseline: 3.6052x; 1.0019x over previous
#include <cuda_runtime.h>
#include <math.h>
#include <stdint.h>

// Problem constants
#define B_    2
#define T_    2048
#define H_    1024
#define NH_   16
#define HD_   64
#define WIN_  256

// Scratch (device globals — allocation-free per harness rules)
__device__ float g_qkv[(size_t)B_ * T_ * 3 * H_];   // [B,T,3H]
__device__ float g_att[(size_t)B_ * T_ * H_];       // [B,T,H] attention output

__device__ __forceinline__ float f2tf32(float x) {
    uint32_t u;
    asm("cvt.rna.tf32.f32 %0, %1;" : "=r"(u) : "f"(x));
    return __uint_as_float(u);
}

__device__ __forceinline__ uint32_t ld_tf32(const float* p) {
    uint32_t u;
    asm("cvt.rna.tf32.f32 %0, %1;" : "=r"(u) : "f"(*p));
    return u;
}

__device__ __forceinline__ void mma_tf32(float c[4], const uint32_t a[4], const uint32_t b[2]) {
    asm volatile(
        "mma.sync.aligned.m16n8k8.row.col.f32.tf32.tf32.f32 "
        "{%0,%1,%2,%3}, {%4,%5,%6,%7}, {%8,%9}, {%0,%1,%2,%3};"
        : "+f"(c[0]), "+f"(c[1]), "+f"(c[2]), "+f"(c[3])
        : "r"(a[0]), "r"(a[1]), "r"(a[2]), "r"(a[3]), "r"(b[0]), "r"(b[1]));
}

__device__ __forceinline__ void cp_async16(float* smem_dst, const float* gsrc) {
    uint32_t s = (uint32_t)__cvta_generic_to_shared(smem_dst);
    asm volatile("cp.async.cg.shared.global [%0], [%1], 16;" :: "r"(s), "l"(gsrc));
}
__device__ __forceinline__ void cp_commit() {
    asm volatile("cp.async.commit_group;");
}
template <int N>
__device__ __forceinline__ void cp_wait() {
    asm volatile("cp.async.wait_group %0;" :: "n"(N));
}

// ---------------------------------------------------------------------------
// TF32 tensor-core GEMM with cp.async double buffering.
// C[M,N] = A[M,K] @ Bm[K,N] + bias[N]
// 128x128 block tile, BK=32, 256 threads = 8 warps (2x4), warp tile 64x32.
// Raw fp32 staged in smem via LDGSTS; tf32 cvt applied at fragment load.
// A stride 36, B stride 136 (conflict-free fragment access).
// ---------------------------------------------------------------------------
#define BM 128
#define BN 128
#define BK 32
#define AS_STRIDE 36
#define BS_STRIDE 136
#define STAGE_FLOATS (BM * AS_STRIDE + BK * BS_STRIDE)   // 4608 + 4352 = 8960
#define GEMM_SMEM (2 * STAGE_FLOATS * 4)                 // 71680 B

__global__ __launch_bounds__(256, 2)
void gemm_tf32_bias(const float* __restrict__ A, const float* __restrict__ Bm,
                    const float* __restrict__ bias, float* __restrict__ C,
                    int M, int N, int K)
{
    extern __shared__ float smem[];
    // stage s: As = smem + s*STAGE_FLOATS, Bs = As + BM*AS_STRIDE

    const int tid  = threadIdx.x;
    const int wid  = tid >> 5;
    const int lane = tid & 31;
    const int wm   = wid >> 2;          // 0..1 (M dir)
    const int wn   = wid & 3;           // 0..3 (N dir)
    const int grp  = lane >> 2;         // 0..7
    const int qid  = lane & 3;          // 0..3

    const float* Ab = A  + (size_t)(blockIdx.y * BM) * K;
    const float* Bb = Bm + (size_t)(blockIdx.x * BN);

    // per-thread copy coordinates
    const int aRow0 = tid >> 3;          // row for i-th A float4: aRow0 + i*? -- we use flat
    float acc[4][4][4];
#pragma unroll
    for (int m = 0; m < 4; m++)
#pragma unroll
        for (int n = 0; n < 4; n++)
#pragma unroll
            for (int r = 0; r < 4; r++) acc[m][n][r] = 0.f;

    const int ITER = K / BK;

    // ---- stage loader ----
    auto load_stage = [&](int k0, int s) {
        float* As = smem + s * STAGE_FLOATS;
        float* Bs = As + BM * AS_STRIDE;
#pragma unroll
        for (int i = 0; i < 4; i++) {
            const int flat = tid + i * 256;          // 0..1023
            const int r  = flat >> 3;                // 0..127
            const int c4 = (flat & 7) * 4;           // 0..28
            cp_async16(As + r * AS_STRIDE + c4, Ab + (size_t)r * K + k0 + c4);
        }
#pragma unroll
        for (int i = 0; i < 4; i++) {
            const int flat = tid + i * 256;
            const int r  = flat >> 5;                // 0..31
            const int c4 = (flat & 31) * 4;          // 0..124
            cp_async16(Bs + r * BS_STRIDE + c4, Bb + (size_t)(k0 + r) * N + c4);
        }
        cp_commit();
    };
    (void)aRow0;

    load_stage(0, 0);

    for (int it = 0; it < ITER; it++) {
        if (it + 1 < ITER) {
            load_stage((it + 1) * BK, (it + 1) & 1);
            cp_wait<1>();
        } else {
            cp_wait<0>();
        }
        __syncthreads();

        const float* As = smem + (it & 1) * STAGE_FLOATS;
        const float* Bs = As + BM * AS_STRIDE;

#pragma unroll
        for (int ks = 0; ks < BK / 8; ks++) {
            const int kb = ks * 8;
            uint32_t af[4][4], bf[4][2];
#pragma unroll
            for (int m = 0; m < 4; m++) {
                const int r = wm * 64 + m * 16;
                af[m][0] = ld_tf32(As + (r + grp    ) * AS_STRIDE + kb + qid    );
                af[m][1] = ld_tf32(As + (r + grp + 8) * AS_STRIDE + kb + qid    );
                af[m][2] = ld_tf32(As + (r + grp    ) * AS_STRIDE + kb + qid + 4);
                af[m][3] = ld_tf32(As + (r + grp + 8) * AS_STRIDE + kb + qid + 4);
            }
#pragma unroll
            for (int n = 0; n < 4; n++) {
                const int c = wn * 32 + n * 8 + grp;
                bf[n][0] = ld_tf32(Bs + (kb + qid    ) * BS_STRIDE + c);
                bf[n][1] = ld_tf32(Bs + (kb + qid + 4) * BS_STRIDE + c);
            }
#pragma unroll
            for (int m = 0; m < 4; m++)
#pragma unroll
                for (int n = 0; n < 4; n++)
                    mma_tf32(acc[m][n], af[m], bf[n]);
        }
        __syncthreads();   // all reads done before stage (it+2)&1 == (it&1) overwrite
    }

    // Epilogue with bias
#pragma unroll
    for (int m = 0; m < 4; m++) {
        const int row0 = blockIdx.y * BM + wm * 64 + m * 16 + grp;
#pragma unroll
        for (int n = 0; n < 4; n++) {
            const int col = blockIdx.x * BN + wn * 32 + n * 8 + qid * 2;
            const float b0 = bias[col], b1 = bias[col + 1];
            float2 v0 = make_float2(acc[m][n][0] + b0, acc[m][n][1] + b1);
            float2 v1 = make_float2(acc[m][n][2] + b0, acc[m][n][3] + b1);
            *(float2*)(C + (size_t)row0 * N + col)       = v0;
            *(float2*)(C + (size_t)(row0 + 8) * N + col) = v1;
        }
    }
}

// ---------------------------------------------------------------------------
// Banded causal attention on tensor cores (tf32 mma, flash online softmax).
// Unchanged from R3 (58us, passing).
// ---------------------------------------------------------------------------
#define ATTN_SMEM2 ((64*68*3 + 64*72) * 4)

__global__ __launch_bounds__(128)
void attn_mma_kernel(float* __restrict__ out)
{
    extern __shared__ float sm[];
    float* Qs = sm;                   // [64][68]
    float* Ps = Qs + 64 * 68;         // [64][68]
    float* Ks = Ps + 64 * 68;         // [64][68]
    float* Vs = Ks + 64 * 68;         // [64][72]

    const int qt  = blockIdx.x;
    const int h   = blockIdx.y;
    const int b   = blockIdx.z;
    const int tid = threadIdx.x;
    const int wid  = tid >> 5;
    const int lane = tid & 31;
    const int g = lane >> 2;
    const int q = lane & 3;
    const int r0 = wid * 16;

    const size_t rs = 3 * H_;
    const size_t base_bt = (size_t)b * T_ * rs + (size_t)h * HD_;
    const size_t qbase = base_bt + (size_t)(qt * 64) * rs;

#pragma unroll
    for (int it = 0; it < 8; it++) {
        const int idx = tid + it * 128;
        const int i = idx >> 4, d4 = (idx & 15) << 2;
        float4 v = *(const float4*)&g_qkv[qbase + (size_t)i * rs + d4];
        float4 w;
        w.x = f2tf32(v.x * 0.125f);
        w.y = f2tf32(v.y * 0.125f);
        w.z = f2tf32(v.z * 0.125f);
        w.w = f2tf32(v.w * 0.125f);
        *(float4*)&Qs[i * 68 + d4] = w;
    }

    float oc[8][4];
#pragma unroll
    for (int nt = 0; nt < 8; nt++)
#pragma unroll
        for (int r = 0; r < 4; r++) oc[nt][r] = 0.f;

    float m0 = -1e30f, m1 = -1e30f, l0 = 0.f, l1 = 0.f;

    int kt0 = qt - 4; if (kt0 < 0) kt0 = 0;

    for (int kt = kt0; kt <= qt; kt++) {
        __syncthreads();

        const size_t kbase = base_bt + (size_t)(kt * 64) * rs + H_;
#pragma unroll
        for (int it = 0; it < 8; it++) {
            const int idx = tid + it * 128;
            const int j = idx >> 4, d4 = (idx & 15) << 2;
            float4 kv = *(const float4*)&g_qkv[kbase + (size_t)j * rs + d4];
            float4 vv = *(const float4*)&g_qkv[kbase + H_ + (size_t)j * rs + d4];
            float4 kw, vw;
            kw.x = f2tf32(kv.x); kw.y = f2tf32(kv.y); kw.z = f2tf32(kv.z); kw.w = f2tf32(kv.w);
            vw.x = f2tf32(vv.x); vw.y = f2tf32(vv.y); vw.z = f2tf32(vv.z); vw.w = f2tf32(vv.w);
            *(float4*)&Ks[j * 68 + d4] = kw;
            *(float4*)&Vs[j * 72 + d4] = vw;
        }
        __syncthreads();

        float s[8][4];
#pragma unroll
        for (int nt = 0; nt < 8; nt++)
#pragma unroll
            for (int r = 0; r < 4; r++) s[nt][r] = 0.f;

#pragma unroll
        for (int ks = 0; ks < 8; ks++) {
            const int kb = ks * 8;
            uint32_t a[4];
            a[0] = __float_as_uint(Qs[(r0 + g    ) * 68 + kb + q    ]);
            a[1] = __float_as_uint(Qs[(r0 + g + 8) * 68 + kb + q    ]);
            a[2] = __float_as_uint(Qs[(r0 + g    ) * 68 + kb + q + 4]);
            a[3] = __float_as_uint(Qs[(r0 + g + 8) * 68 + kb + q + 4]);
#pragma unroll
            for (int nt = 0; nt < 8; nt++) {
                uint32_t bb[2];
                bb[0] = __float_as_uint(Ks[(nt * 8 + g) * 68 + kb + q    ]);
                bb[1] = __float_as_uint(Ks[(nt * 8 + g) * 68 + kb + q + 4]);
                mma_tf32(s[nt], a, bb);
            }
        }

        const int ig0 = qt * 64 + r0 + g;
        const int ig1 = ig0 + 8;
#pragma unroll
        for (int nt = 0; nt < 8; nt++) {
            const int jg = kt * 64 + nt * 8 + 2 * q;
            int d00 = ig0 - jg;     if (d00 < 0 || d00 >= WIN_) s[nt][0] = -1e30f;
            int d01 = ig0 - jg - 1; if (d01 < 0 || d01 >= WIN_) s[nt][1] = -1e30f;
            int d10 = ig1 - jg;     if (d10 < 0 || d10 >= WIN_) s[nt][2] = -1e30f;
            int d11 = ig1 - jg - 1; if (d11 < 0 || d11 >= WIN_) s[nt][3] = -1e30f;
        }
        float mx0 = -1e30f, mx1 = -1e30f;
#pragma unroll
        for (int nt = 0; nt < 8; nt++) {
            mx0 = fmaxf(mx0, fmaxf(s[nt][0], s[nt][1]));
            mx1 = fmaxf(mx1, fmaxf(s[nt][2], s[nt][3]));
        }
        mx0 = fmaxf(mx0, __shfl_xor_sync(0xffffffffu, mx0, 1));
        mx0 = fmaxf(mx0, __shfl_xor_sync(0xffffffffu, mx0, 2));
        mx1 = fmaxf(mx1, __shfl_xor_sync(0xffffffffu, mx1, 1));
        mx1 = fmaxf(mx1, __shfl_xor_sync(0xffffffffu, mx1, 2));

        const float mn0 = fmaxf(m0, mx0), mn1 = fmaxf(m1, mx1);
        const float e0 = __expf(m0 - mn0), e1 = __expf(m1 - mn1);
        float rs0 = 0.f, rs1 = 0.f;
#pragma unroll
        for (int nt = 0; nt < 8; nt++) {
            const float p00 = __expf(s[nt][0] - mn0);
            const float p01 = __expf(s[nt][1] - mn0);
            const float p10 = __expf(s[nt][2] - mn1);
            const float p11 = __expf(s[nt][3] - mn1);
            rs0 += p00 + p01;
            rs1 += p10 + p11;
            float2 v0 = make_float2(f2tf32(p00), f2tf32(p01));
            float2 v1 = make_float2(f2tf32(p10), f2tf32(p11));
            *(float2*)&Ps[(r0 + g    ) * 68 + nt * 8 + 2 * q] = v0;
            *(float2*)&Ps[(r0 + g + 8) * 68 + nt * 8 + 2 * q] = v1;
        }
        rs0 += __shfl_xor_sync(0xffffffffu, rs0, 1);
        rs0 += __shfl_xor_sync(0xffffffffu, rs0, 2);
        rs1 += __shfl_xor_sync(0xffffffffu, rs1, 1);
        rs1 += __shfl_xor_sync(0xffffffffu, rs1, 2);

        l0 = l0 * e0 + rs0;  m0 = mn0;
        l1 = l1 * e1 + rs1;  m1 = mn1;

#pragma unroll
        for (int nt = 0; nt < 8; nt++) {
            oc[nt][0] *= e0; oc[nt][1] *= e0;
            oc[nt][2] *= e1; oc[nt][3] *= e1;
        }
        __syncthreads();

#pragma unroll
        for (int ks = 0; ks < 8; ks++) {
            const int kb = ks * 8;
            uint32_t a[4];
            a[0] = __float_as_uint(Ps[(r0 + g    ) * 68 + kb + q    ]);
            a[1] = __float_as_uint(Ps[(r0 + g + 8) * 68 + kb + q    ]);
            a[2] = __float_as_uint(Ps[(r0 + g    ) * 68 + kb + q + 4]);
            a[3] = __float_as_uint(Ps[(r0 + g + 8) * 68 + kb + q + 4]);
#pragma unroll
            for (int nt = 0; nt < 8; nt++) {
                uint32_t bb[2];
                bb[0] = __float_as_uint(Vs[(kb + q    ) * 72 + nt * 8 + g]);
                bb[1] = __float_as_uint(Vs[(kb + q + 4) * 72 + nt * 8 + g]);
                mma_tf32(oc[nt], a, bb);
            }
        }
    }

    const float inv0 = 1.f / l0, inv1 = 1.f / l1;
    const int row0g = qt * 64 + r0 + g;
#pragma unroll
    for (int nt = 0; nt < 8; nt++) {
        const int col = h * HD_ + nt * 8 + 2 * q;
        float2 v0 = make_float2(oc[nt][0] * inv0, oc[nt][1] * inv0);
        float2 v1 = make_float2(oc[nt][2] * inv1, oc[nt][3] * inv1);
        *(float2*)&out[(size_t)(b * T_ + row0g    ) * H_ + col] = v0;
        *(float2*)&out[(size_t)(b * T_ + row0g + 8) * H_ + col] = v1;
    }
}

// ---------------------------------------------------------------------------
// Launch: qkv GEMM -> banded attention (mma) -> out GEMM
// ---------------------------------------------------------------------------
extern "C" void kernel_launch(void* const* d_in, const int* in_sizes, int n_in,
                              void* d_out, int out_size)
{
    const float* x     = (const float*)d_in[0];
    const float* W_qkv = (const float*)d_in[1];
    const float* b_qkv = (const float*)d_in[2];
    const float* W_out = (const float*)d_in[3];
    const float* b_out = (const float*)d_in[4];
    float* out = (float*)d_out;

    float* qkv; cudaGetSymbolAddress((void**)&qkv, g_qkv);
    float* att; cudaGetSymbolAddress((void**)&att, g_att);

    const int M = B_ * T_;

    cudaFuncSetAttribute(gemm_tf32_bias,
                         cudaFuncAttributeMaxDynamicSharedMemorySize, GEMM_SMEM);
    {
        dim3 grid((3 * H_) / BN, M / BM);
        gemm_tf32_bias<<<grid, 256, GEMM_SMEM>>>(x, W_qkv, b_qkv, qkv, M, 3 * H_, H_);
    }
    {
        cudaFuncSetAttribute(attn_mma_kernel,
                             cudaFuncAttributeMaxDynamicSharedMemorySize, ATTN_SMEM2);
        dim3 grid(T_ / 64, NH_, B_);
        attn_mma_kernel<<<grid, 128, ATTN_SMEM2>>>(att);
    }
    {
        dim3 grid(H_ / BN, M / BM);
        gemm_tf32_bias<<<grid, 256, GEMM_SMEM>>>(att, W_out, b_out, out, M, H_, H_);
    }
}